// round 1
// baseline (speedup 1.0000x reference)
#include <cuda_runtime.h>
#include <cuda_bf16.h>
#include <math.h>

// Problem constants (fixed by the reference).
#define N_NODES 100000
#define E_EDGES 1600000
#define FDIM    128
#define GGRAPHS 64
#define COUT    10

// -------------------- scratch (static device globals; no allocs) ------------
__device__ int   g_deg[N_NODES];
__device__ int   g_rowptr[N_NODES + 1];
__device__ int   g_cursor[N_NODES];
__device__ int   g_csr[E_EDGES];
__device__ float g_agg[(size_t)N_NODES * FDIM];
__device__ float g_hA[(size_t)N_NODES * FDIM];
__device__ float g_hB[(size_t)N_NODES * FDIM];
__device__ float g_pooled[GGRAPHS * FDIM];

// -------------------- CSR build ---------------------------------------------
__global__ void k_zero_deg() {
    int i = blockIdx.x * blockDim.x + threadIdx.x;
    if (i < N_NODES) g_deg[i] = 0;
}

__global__ void k_hist(const int* __restrict__ ei) {
    int e = blockIdx.x * blockDim.x + threadIdx.x;
    if (e < E_EDGES) atomicAdd(&g_deg[ei[E_EDGES + e]], 1);
}

// single-block exclusive scan of g_deg -> g_rowptr / g_cursor
__global__ void k_scan() {
    __shared__ int tsum[1024];
    const int T = 1024;
    int tid = threadIdx.x;
    int per = (N_NODES + T - 1) / T;                 // 98
    int b = tid * per;
    int e = min(b + per, N_NODES);
    int s = 0;
    for (int i = b; i < e; i++) s += g_deg[i];
    tsum[tid] = s;
    __syncthreads();
    for (int d = 1; d < T; d <<= 1) {
        int v = (tid >= d) ? tsum[tid - d] : 0;
        __syncthreads();
        tsum[tid] += v;
        __syncthreads();
    }
    int off = (tid == 0) ? 0 : tsum[tid - 1];
    for (int i = b; i < e; i++) {
        g_rowptr[i] = off;
        g_cursor[i] = off;
        off += g_deg[i];
    }
    if (tid == T - 1) g_rowptr[N_NODES] = off;       // == E_EDGES
}

__global__ void k_fill(const int* __restrict__ ei) {
    int e = blockIdx.x * blockDim.x + threadIdx.x;
    if (e < E_EDGES) {
        int d = ei[E_EDGES + e];
        int p = atomicAdd(&g_cursor[d], 1);
        g_csr[p] = ei[e];
    }
}

// -------------------- aggregation (warp per node, no atomics) ---------------
__global__ void k_aggregate(const float* __restrict__ xin) {
    int warp = (blockIdx.x * blockDim.x + threadIdx.x) >> 5;
    if (warp >= N_NODES) return;
    int lane = threadIdx.x & 31;
    int beg = g_rowptr[warp];
    int end = g_rowptr[warp + 1];
    float4 acc = make_float4(0.f, 0.f, 0.f, 0.f);
    for (int e = beg; e < end; e++) {
        int s = g_csr[e];
        float4 v = __ldg((const float4*)(xin + (size_t)s * FDIM) + lane);
        acc.x += v.x; acc.y += v.y; acc.z += v.z; acc.w += v.w;
    }
    ((float4*)(g_agg + (size_t)warp * FDIM))[lane] = acc;
}

// -------------------- fused GEMM: out = relu(agg@Wr^T + x@Wo^T + b) ---------
#define BM 64
#define BN 128
#define BK 16

__global__ __launch_bounds__(256) void k_gemm_fused(
    const float* __restrict__ Aagg, const float* __restrict__ Ax,
    const float* __restrict__ Wrel, const float* __restrict__ Wroot,
    const float* __restrict__ bias, float* __restrict__ out)
{
    __shared__ __align__(16) float sAa[BK][BM];
    __shared__ __align__(16) float sAx[BK][BM];
    __shared__ __align__(16) float sWr[BK][BN];
    __shared__ __align__(16) float sWo[BK][BN];

    int tid = threadIdx.x;
    int tx = tid & 15;            // 0..15 -> 8 output cols each
    int ty = tid >> 4;            // 0..15 -> 4 output rows each
    int m0 = blockIdx.x * BM;

    float acc[4][8];
#pragma unroll
    for (int i = 0; i < 4; i++)
#pragma unroll
        for (int j = 0; j < 8; j++) acc[i][j] = 0.f;

    for (int kk = 0; kk < FDIM; kk += BK) {
        // A tiles: 64 rows x 16 k = 256 float4, one per thread
        {
            int r  = tid >> 2;     // 0..63
            int kv = tid & 3;      // float4 within the 16-k chunk
            int gm = m0 + r;
            float4 va = make_float4(0.f, 0.f, 0.f, 0.f);
            float4 vx = make_float4(0.f, 0.f, 0.f, 0.f);
            if (gm < N_NODES) {
                va = *(const float4*)(Aagg + (size_t)gm * FDIM + kk + kv * 4);
                vx = *(const float4*)(Ax   + (size_t)gm * FDIM + kk + kv * 4);
            }
            sAa[kv * 4 + 0][r] = va.x; sAa[kv * 4 + 1][r] = va.y;
            sAa[kv * 4 + 2][r] = va.z; sAa[kv * 4 + 3][r] = va.w;
            sAx[kv * 4 + 0][r] = vx.x; sAx[kv * 4 + 1][r] = vx.y;
            sAx[kv * 4 + 2][r] = vx.z; sAx[kv * 4 + 3][r] = vx.w;
        }
        // W tiles: 128 n x 16 k = 512 float4, two per thread
        {
#pragma unroll
            for (int i = 0; i < 2; i++) {
                int idx = tid + i * 256;   // 0..511
                int n   = idx >> 2;        // 0..127
                int kv  = idx & 3;
                float4 wr = *(const float4*)(Wrel  + n * FDIM + kk + kv * 4);
                float4 wo = *(const float4*)(Wroot + n * FDIM + kk + kv * 4);
                sWr[kv * 4 + 0][n] = wr.x; sWr[kv * 4 + 1][n] = wr.y;
                sWr[kv * 4 + 2][n] = wr.z; sWr[kv * 4 + 3][n] = wr.w;
                sWo[kv * 4 + 0][n] = wo.x; sWo[kv * 4 + 1][n] = wo.y;
                sWo[kv * 4 + 2][n] = wo.z; sWo[kv * 4 + 3][n] = wo.w;
            }
        }
        __syncthreads();

#pragma unroll
        for (int k = 0; k < BK; k++) {
            float4 aa = *(const float4*)&sAa[k][ty * 4];
            float4 ax = *(const float4*)&sAx[k][ty * 4];
            float4 wr0 = *(const float4*)&sWr[k][tx * 8];
            float4 wr1 = *(const float4*)&sWr[k][tx * 8 + 4];
            float4 wo0 = *(const float4*)&sWo[k][tx * 8];
            float4 wo1 = *(const float4*)&sWo[k][tx * 8 + 4];
            float a[4] = {aa.x, aa.y, aa.z, aa.w};
            float x[4] = {ax.x, ax.y, ax.z, ax.w};
            float wr[8] = {wr0.x, wr0.y, wr0.z, wr0.w, wr1.x, wr1.y, wr1.z, wr1.w};
            float wo[8] = {wo0.x, wo0.y, wo0.z, wo0.w, wo1.x, wo1.y, wo1.z, wo1.w};
#pragma unroll
            for (int i = 0; i < 4; i++)
#pragma unroll
                for (int j = 0; j < 8; j++)
                    acc[i][j] += a[i] * wr[j] + x[i] * wo[j];
        }
        __syncthreads();
    }

    // epilogue: + bias, relu, store
#pragma unroll
    for (int i = 0; i < 4; i++) {
        int gm = m0 + ty * 4 + i;
        if (gm >= N_NODES) continue;
        float4 o0, o1;
        int n = tx * 8;
        o0.x = fmaxf(acc[i][0] + __ldg(&bias[n + 0]), 0.f);
        o0.y = fmaxf(acc[i][1] + __ldg(&bias[n + 1]), 0.f);
        o0.z = fmaxf(acc[i][2] + __ldg(&bias[n + 2]), 0.f);
        o0.w = fmaxf(acc[i][3] + __ldg(&bias[n + 3]), 0.f);
        o1.x = fmaxf(acc[i][4] + __ldg(&bias[n + 4]), 0.f);
        o1.y = fmaxf(acc[i][5] + __ldg(&bias[n + 5]), 0.f);
        o1.z = fmaxf(acc[i][6] + __ldg(&bias[n + 6]), 0.f);
        o1.w = fmaxf(acc[i][7] + __ldg(&bias[n + 7]), 0.f);
        *(float4*)(out + (size_t)gm * FDIM + n)     = o0;
        *(float4*)(out + (size_t)gm * FDIM + n + 4) = o1;
    }
}

// -------------------- mean pool over sorted batch ids -----------------------
__global__ void k_pool(const float* __restrict__ h, const int* __restrict__ batch) {
    int g = blockIdx.x;        // 0..63
    int t = threadIdx.x;       // 0..127
    // lower_bound(batch, key)
    int lo = 0, hi = N_NODES;
    {
        int key = g;
        int a = 0, b = N_NODES;
        while (a < b) { int m = (a + b) >> 1; if (batch[m] < key) a = m + 1; else b = m; }
        lo = a;
        key = g + 1; a = lo; b = N_NODES;
        while (a < b) { int m = (a + b) >> 1; if (batch[m] < key) a = m + 1; else b = m; }
        hi = a;
    }
    float s = 0.f;
    for (int n = lo; n < hi; n++) s += h[(size_t)n * FDIM + t];
    float c = (float)max(hi - lo, 1);
    g_pooled[g * FDIM + t] = s / c;
}

// -------------------- MLP head + log_softmax --------------------------------
__global__ void k_mlp(const float* __restrict__ Wl1, const float* __restrict__ bl1,
                      const float* __restrict__ Wl2, const float* __restrict__ bl2,
                      float* __restrict__ out)
{
    int g = blockIdx.x;       // graph
    int t = threadIdx.x;      // 0..63
    __shared__ float p[FDIM];
    __shared__ float h1[64];
    __shared__ float lg[COUT];
    p[t]      = g_pooled[g * FDIM + t];
    p[t + 64] = g_pooled[g * FDIM + 64 + t];
    __syncthreads();
    float s = bl1[t];
#pragma unroll 8
    for (int k = 0; k < FDIM; k++) s += p[k] * Wl1[t * FDIM + k];
    h1[t] = fmaxf(s, 0.f);
    __syncthreads();
    if (t < COUT) {
        float s2 = bl2[t];
#pragma unroll 8
        for (int k = 0; k < 64; k++) s2 += h1[k] * Wl2[t * 64 + k];
        lg[t] = s2;
    }
    __syncthreads();
    if (t == 0) {
        float mx = -INFINITY;
        for (int c = 0; c < COUT; c++) mx = fmaxf(mx, lg[c]);
        float se = 0.f;
        for (int c = 0; c < COUT; c++) se += expf(lg[c] - mx);
        float lse = logf(se) + mx;
        for (int c = 0; c < COUT; c++) out[g * COUT + c] = lg[c] - lse;
    }
}

// -------------------- launch ------------------------------------------------
extern "C" void kernel_launch(void* const* d_in, const int* in_sizes, int n_in,
                              void* d_out, int out_size)
{
    const float* x     = (const float*)d_in[0];
    const int*   ei    = (const int*)d_in[1];
    const int*   batch = (const int*)d_in[2];
    // target_size may or may not appear as a scalar input right after batch
    int wb = 3;
    if (n_in > 3 && in_sizes[3] <= 4) wb = 4;
    const float* W1r = (const float*)d_in[wb + 0];
    const float* b1  = (const float*)d_in[wb + 1];
    const float* W1o = (const float*)d_in[wb + 2];
    const float* W2r = (const float*)d_in[wb + 3];
    const float* b2  = (const float*)d_in[wb + 4];
    const float* W2o = (const float*)d_in[wb + 5];
    const float* W3r = (const float*)d_in[wb + 6];
    const float* b3  = (const float*)d_in[wb + 7];
    const float* W3o = (const float*)d_in[wb + 8];
    const float* Wl1 = (const float*)d_in[wb + 9];
    const float* bl1 = (const float*)d_in[wb + 10];
    const float* Wl2 = (const float*)d_in[wb + 11];
    const float* bl2 = (const float*)d_in[wb + 12];
    float* out = (float*)d_out;

    float* hA; float* hB; float* agg;
    cudaGetSymbolAddress((void**)&hA,  g_hA);
    cudaGetSymbolAddress((void**)&hB,  g_hB);
    cudaGetSymbolAddress((void**)&agg, g_agg);

    // CSR build (once per launch, reused by all 3 layers)
    k_zero_deg<<<(N_NODES + 255) / 256, 256>>>();
    k_hist<<<(E_EDGES + 255) / 256, 256>>>(ei);
    k_scan<<<1, 1024>>>();
    k_fill<<<(E_EDGES + 255) / 256, 256>>>(ei);

    int aggBlocks  = (N_NODES * 32 + 255) / 256;
    int gemmBlocks = (N_NODES + BM - 1) / BM;

    // layer 1: x -> hA
    k_aggregate<<<aggBlocks, 256>>>(x);
    k_gemm_fused<<<gemmBlocks, 256>>>(agg, x, W1r, W1o, b1, hA);
    // layer 2: hA -> hB
    k_aggregate<<<aggBlocks, 256>>>(hA);
    k_gemm_fused<<<gemmBlocks, 256>>>(agg, hA, W2r, W2o, b2, hB);
    // layer 3: hB -> hA
    k_aggregate<<<aggBlocks, 256>>>(hB);
    k_gemm_fused<<<gemmBlocks, 256>>>(agg, hB, W3r, W3o, b3, hA);

    // pool + MLP head
    k_pool<<<GGRAPHS, 128>>>(hA, batch);
    k_mlp<<<GGRAPHS, 64>>>(Wl1, bl1, Wl2, bl2, out);
}

// round 3
// speedup vs baseline: 1.4434x; 1.4434x over previous
#include <cuda_runtime.h>
#include <cuda_bf16.h>
#include <math.h>

#define N_NODES 100000
#define E_EDGES 1600000
#define FDIM    128
#define GGRAPHS 64
#define COUT    10

// -------------------- scratch (static device globals) -----------------------
__device__ int   g_deg[N_NODES];
__device__ int   g_rowptr[N_NODES + 1];
__device__ int   g_cursor[N_NODES];
__device__ int   g_csr[E_EDGES];
__device__ float g_xr[(size_t)N_NODES * FDIM];
__device__ float g_xo[(size_t)N_NODES * FDIM];
__device__ float g_hA[(size_t)N_NODES * FDIM];
__device__ float g_hB[(size_t)N_NODES * FDIM];
__device__ float g_pooled[GGRAPHS * FDIM];

// -------------------- CSR build ---------------------------------------------
__global__ void k_zero_deg() {
    int i = blockIdx.x * blockDim.x + threadIdx.x;
    if (i < N_NODES) g_deg[i] = 0;
}

__global__ void k_hist(const int* __restrict__ ei) {
    int e = blockIdx.x * blockDim.x + threadIdx.x;
    if (e < E_EDGES) atomicAdd(&g_deg[ei[E_EDGES + e]], 1);
}

__global__ void k_scan() {
    __shared__ int tsum[1024];
    const int T = 1024;
    int tid = threadIdx.x;
    int per = (N_NODES + T - 1) / T;
    int b = tid * per;
    int e = min(b + per, N_NODES);
    int s = 0;
    for (int i = b; i < e; i++) s += g_deg[i];
    tsum[tid] = s;
    __syncthreads();
    for (int d = 1; d < T; d <<= 1) {
        int v = (tid >= d) ? tsum[tid - d] : 0;
        __syncthreads();
        tsum[tid] += v;
        __syncthreads();
    }
    int off = (tid == 0) ? 0 : tsum[tid - 1];
    for (int i = b; i < e; i++) {
        g_rowptr[i] = off;
        g_cursor[i] = off;
        off += g_deg[i];
    }
    if (tid == T - 1) g_rowptr[N_NODES] = off;
}

__global__ void k_fill(const int* __restrict__ ei) {
    int e = blockIdx.x * blockDim.x + threadIdx.x;
    if (e < E_EDGES) {
        int d = ei[E_EDGES + e];
        int p = atomicAdd(&g_cursor[d], 1);
        g_csr[p] = ei[e];
    }
}

// -------------------- TF32 mma GEMM: C[M,128] = A[M,128] @ W[128,128]^T -----
__device__ __forceinline__ unsigned f2tf(float f) {
    unsigned u;
    asm("cvt.rna.tf32.f32 %0, %1;" : "=r"(u) : "f"(f));
    return u;
}

__device__ __forceinline__ void mma8(float* c, const unsigned* a, unsigned b0, unsigned b1) {
    asm volatile(
        "mma.sync.aligned.m16n8k8.row.col.f32.tf32.tf32.f32 "
        "{%0,%1,%2,%3},{%4,%5,%6,%7},{%8,%9},{%0,%1,%2,%3};"
        : "+f"(c[0]), "+f"(c[1]), "+f"(c[2]), "+f"(c[3])
        : "r"(a[0]), "r"(a[1]), "r"(a[2]), "r"(a[3]), "r"(b0), "r"(b1));
}

// Block tile 128(M) x 128(N), BK=32, 8 warps, warp tile 32x64.
// 3xTF32 split (hi*hi + hi*lo + lo*hi) for fp32-grade accuracy.
__global__ __launch_bounds__(256) void k_gemm_tf32(
    const float* __restrict__ A, const float* __restrict__ W,
    float* __restrict__ C, int M)
{
    __shared__ __align__(16) float sA[128][36];
    __shared__ __align__(16) float sB[128][36];
    int tid = threadIdx.x;
    int m0 = blockIdx.x * 128;
    int warp = tid >> 5, lane = tid & 31;
    int wm = warp >> 1, wn = warp & 1;
    int gq = lane >> 2, t4 = lane & 3;

    float acc[2][8][4];
#pragma unroll
    for (int i = 0; i < 2; i++)
#pragma unroll
        for (int j = 0; j < 8; j++)
#pragma unroll
            for (int q = 0; q < 4; q++) acc[i][j][q] = 0.f;

    for (int kk = 0; kk < FDIM; kk += 32) {
#pragma unroll
        for (int i = 0; i < 4; i++) {
            int f = tid + i * 256;          // 0..1023
            int r = f >> 3, c4 = f & 7;     // row, float4-within-32k
            float4 v = make_float4(0.f, 0.f, 0.f, 0.f);
            if (m0 + r < M)
                v = *(const float4*)(A + (size_t)(m0 + r) * FDIM + kk + c4 * 4);
            *(float4*)&sA[r][c4 * 4] = v;
            float4 w = *(const float4*)(W + r * FDIM + kk + c4 * 4);
            *(float4*)&sB[r][c4 * 4] = w;
        }
        __syncthreads();

#pragma unroll
        for (int k8 = 0; k8 < 4; k8++) {
            int kc = k8 * 8 + t4;
            unsigned ahi[2][4], alo[2][4];
#pragma unroll
            for (int mt = 0; mt < 2; mt++) {
                int r = wm * 32 + mt * 16 + gq;
                float f0 = sA[r][kc];
                float f1 = sA[r + 8][kc];
                float f2 = sA[r][kc + 4];
                float f3 = sA[r + 8][kc + 4];
                ahi[mt][0] = f2tf(f0); alo[mt][0] = f2tf(f0 - __uint_as_float(ahi[mt][0]));
                ahi[mt][1] = f2tf(f1); alo[mt][1] = f2tf(f1 - __uint_as_float(ahi[mt][1]));
                ahi[mt][2] = f2tf(f2); alo[mt][2] = f2tf(f2 - __uint_as_float(ahi[mt][2]));
                ahi[mt][3] = f2tf(f3); alo[mt][3] = f2tf(f3 - __uint_as_float(ahi[mt][3]));
            }
#pragma unroll
            for (int nt = 0; nt < 8; nt++) {
                int n = wn * 64 + nt * 8 + gq;
                float g0 = sB[n][kc];
                float g1 = sB[n][kc + 4];
                unsigned bh0 = f2tf(g0), bh1 = f2tf(g1);
                unsigned bl0 = f2tf(g0 - __uint_as_float(bh0));
                unsigned bl1 = f2tf(g1 - __uint_as_float(bh1));
#pragma unroll
                for (int mt = 0; mt < 2; mt++) {
                    mma8(acc[mt][nt], alo[mt], bh0, bh1);
                    mma8(acc[mt][nt], ahi[mt], bl0, bl1);
                    mma8(acc[mt][nt], ahi[mt], bh0, bh1);
                }
            }
        }
        __syncthreads();
    }

#pragma unroll
    for (int mt = 0; mt < 2; mt++) {
#pragma unroll
        for (int nt = 0; nt < 8; nt++) {
            int r0 = m0 + wm * 32 + mt * 16 + gq;
            int cc = wn * 64 + nt * 8 + t4 * 2;
            if (r0 < M) {
                float2 o; o.x = acc[mt][nt][0]; o.y = acc[mt][nt][1];
                *(float2*)(C + (size_t)r0 * FDIM + cc) = o;
            }
            if (r0 + 8 < M) {
                float2 o; o.x = acc[mt][nt][2]; o.y = acc[mt][nt][3];
                *(float2*)(C + (size_t)(r0 + 8) * FDIM + cc) = o;
            }
        }
    }
}

// ----- fused: out_i = relu( sum_{j->i} xr[j] + xo[i] + bias ) ---------------
__global__ void k_agg_combine(const float* __restrict__ xr,
                              const float* __restrict__ xo,
                              const float* __restrict__ bias,
                              float* __restrict__ out)
{
    int node = (blockIdx.x * blockDim.x + threadIdx.x) >> 5;
    if (node >= N_NODES) return;
    int lane = threadIdx.x & 31;
    int beg = g_rowptr[node];
    int end = g_rowptr[node + 1];
    float4 acc = make_float4(0.f, 0.f, 0.f, 0.f);
    int e = beg;
    for (; e + 2 <= end; e += 2) {
        int s0 = g_csr[e];
        int s1 = g_csr[e + 1];
        float4 v0 = __ldg((const float4*)(xr + (size_t)s0 * FDIM) + lane);
        float4 v1 = __ldg((const float4*)(xr + (size_t)s1 * FDIM) + lane);
        acc.x += v0.x + v1.x; acc.y += v0.y + v1.y;
        acc.z += v0.z + v1.z; acc.w += v0.w + v1.w;
    }
    if (e < end) {
        int s0 = g_csr[e];
        float4 v0 = __ldg((const float4*)(xr + (size_t)s0 * FDIM) + lane);
        acc.x += v0.x; acc.y += v0.y; acc.z += v0.z; acc.w += v0.w;
    }
    float4 o = __ldg((const float4*)(xo + (size_t)node * FDIM) + lane);
    float4 b = __ldg((const float4*)bias + lane);
    float4 r;
    r.x = fmaxf(acc.x + o.x + b.x, 0.f);
    r.y = fmaxf(acc.y + o.y + b.y, 0.f);
    r.z = fmaxf(acc.z + o.z + b.z, 0.f);
    r.w = fmaxf(acc.w + o.w + b.w, 0.f);
    ((float4*)(out + (size_t)node * FDIM))[lane] = r;
}

// -------------------- mean pool over sorted batch ids -----------------------
__global__ void k_pool(const float* __restrict__ h, const int* __restrict__ batch) {
    int g = blockIdx.x;
    int t = threadIdx.x;
    int lo, hi;
    {
        int key = g;
        int a = 0, b = N_NODES;
        while (a < b) { int m = (a + b) >> 1; if (batch[m] < key) a = m + 1; else b = m; }
        lo = a;
        key = g + 1; a = lo; b = N_NODES;
        while (a < b) { int m = (a + b) >> 1; if (batch[m] < key) a = m + 1; else b = m; }
        hi = a;
    }
    float s = 0.f;
    for (int n = lo; n < hi; n++) s += h[(size_t)n * FDIM + t];
    float c = (float)max(hi - lo, 1);
    g_pooled[g * FDIM + t] = s / c;
}

// -------------------- MLP head + log_softmax --------------------------------
__global__ void k_mlp(const float* __restrict__ Wl1, const float* __restrict__ bl1,
                      const float* __restrict__ Wl2, const float* __restrict__ bl2,
                      float* __restrict__ out)
{
    int g = blockIdx.x;
    int t = threadIdx.x;
    __shared__ float p[FDIM];
    __shared__ float h1[64];
    __shared__ float lg[COUT];
    p[t]      = g_pooled[g * FDIM + t];
    p[t + 64] = g_pooled[g * FDIM + 64 + t];
    __syncthreads();
    float s = bl1[t];
#pragma unroll 8
    for (int k = 0; k < FDIM; k++) s += p[k] * Wl1[t * FDIM + k];
    h1[t] = fmaxf(s, 0.f);
    __syncthreads();
    if (t < COUT) {
        float s2 = bl2[t];
#pragma unroll 8
        for (int k = 0; k < 64; k++) s2 += h1[k] * Wl2[t * 64 + k];
        lg[t] = s2;
    }
    __syncthreads();
    if (t == 0) {
        float mx = -INFINITY;
        for (int c = 0; c < COUT; c++) mx = fmaxf(mx, lg[c]);
        float se = 0.f;
        for (int c = 0; c < COUT; c++) se += expf(lg[c] - mx);
        float lse = logf(se) + mx;
        for (int c = 0; c < COUT; c++) out[g * COUT + c] = lg[c] - lse;
    }
}

// -------------------- launch ------------------------------------------------
extern "C" void kernel_launch(void* const* d_in, const int* in_sizes, int n_in,
                              void* d_out, int out_size)
{
    const float* x     = (const float*)d_in[0];
    const int*   ei    = (const int*)d_in[1];
    const int*   batch = (const int*)d_in[2];
    int wb = 3;
    if (n_in > 3 && in_sizes[3] <= 4) wb = 4;
    const float* W1r = (const float*)d_in[wb + 0];
    const float* b1  = (const float*)d_in[wb + 1];
    const float* W1o = (const float*)d_in[wb + 2];
    const float* W2r = (const float*)d_in[wb + 3];
    const float* b2  = (const float*)d_in[wb + 4];
    const float* W2o = (const float*)d_in[wb + 5];
    const float* W3r = (const float*)d_in[wb + 6];
    const float* b3  = (const float*)d_in[wb + 7];
    const float* W3o = (const float*)d_in[wb + 8];
    const float* Wl1 = (const float*)d_in[wb + 9];
    const float* bl1 = (const float*)d_in[wb + 10];
    const float* Wl2 = (const float*)d_in[wb + 11];
    const float* bl2 = (const float*)d_in[wb + 12];
    float* out = (float*)d_out;

    float *xr, *xo, *hA, *hB;
    cudaGetSymbolAddress((void**)&xr, g_xr);
    cudaGetSymbolAddress((void**)&xo, g_xo);
    cudaGetSymbolAddress((void**)&hA, g_hA);
    cudaGetSymbolAddress((void**)&hB, g_hB);

    // CSR build (once, reused by all 3 layers)
    k_zero_deg<<<(N_NODES + 255) / 256, 256>>>();
    k_hist<<<(E_EDGES + 255) / 256, 256>>>(ei);
    k_scan<<<1, 1024>>>();
    k_fill<<<(E_EDGES + 255) / 256, 256>>>(ei);

    int gemmBlocks = (N_NODES + 127) / 128;
    int aggBlocks  = (N_NODES * 32 + 255) / 256;

    // layer 1: x -> hA   (transform-first: xr = x@Wr^T, xo = x@Wo^T)
    k_gemm_tf32<<<gemmBlocks, 256>>>(x, W1r, xr, N_NODES);
    k_gemm_tf32<<<gemmBlocks, 256>>>(x, W1o, xo, N_NODES);
    k_agg_combine<<<aggBlocks, 256>>>(xr, xo, b1, hA);
    // layer 2: hA -> hB
    k_gemm_tf32<<<gemmBlocks, 256>>>(hA, W2r, xr, N_NODES);
    k_gemm_tf32<<<gemmBlocks, 256>>>(hA, W2o, xo, N_NODES);
    k_agg_combine<<<aggBlocks, 256>>>(xr, xo, b2, hB);
    // layer 3: hB -> hA
    k_gemm_tf32<<<gemmBlocks, 256>>>(hB, W3r, xr, N_NODES);
    k_gemm_tf32<<<gemmBlocks, 256>>>(hB, W3o, xo, N_NODES);
    k_agg_combine<<<aggBlocks, 256>>>(xr, xo, b3, hA);

    // pool + head
    k_pool<<<GGRAPHS, 128>>>(hA, batch);
    k_mlp<<<GGRAPHS, 64>>>(Wl1, bl1, Wl2, bl2, out);
}

// round 4
// speedup vs baseline: 1.8146x; 1.2572x over previous
#include <cuda_runtime.h>
#include <cuda_bf16.h>
#include <math.h>

#define N_NODES 100000
#define E_EDGES 1600000
#define FDIM    128
#define GGRAPHS 64
#define COUT    10

// -------------------- scratch (static device globals) -----------------------
__device__ int   g_deg[N_NODES];
__device__ int   g_rowptr[N_NODES + 1];
__device__ int   g_cursor[N_NODES];
__device__ int   g_csr[E_EDGES];
__device__ float g_xr[(size_t)N_NODES * FDIM];
__device__ float g_xo[(size_t)N_NODES * FDIM];
__device__ float g_hA[(size_t)N_NODES * FDIM];
__device__ float g_hB[(size_t)N_NODES * FDIM];
__device__ float g_pooled[GGRAPHS * FDIM];

// -------------------- CSR build ---------------------------------------------
__global__ void k_zero_deg() {
    int i = blockIdx.x * blockDim.x + threadIdx.x;
    if (i < N_NODES) g_deg[i] = 0;
}

__global__ void k_hist(const int* __restrict__ ei) {
    int e = blockIdx.x * blockDim.x + threadIdx.x;
    if (e < E_EDGES) atomicAdd(&g_deg[ei[E_EDGES + e]], 1);
}

__global__ void k_scan() {
    __shared__ int tsum[1024];
    const int T = 1024;
    int tid = threadIdx.x;
    int per = (N_NODES + T - 1) / T;
    int b = tid * per;
    int e = min(b + per, N_NODES);
    int s = 0;
    for (int i = b; i < e; i++) s += g_deg[i];
    tsum[tid] = s;
    __syncthreads();
    for (int d = 1; d < T; d <<= 1) {
        int v = (tid >= d) ? tsum[tid - d] : 0;
        __syncthreads();
        tsum[tid] += v;
        __syncthreads();
    }
    int off = (tid == 0) ? 0 : tsum[tid - 1];
    for (int i = b; i < e; i++) {
        g_rowptr[i] = off;
        g_cursor[i] = off;
        off += g_deg[i];
    }
    if (tid == T - 1) g_rowptr[N_NODES] = off;
}

__global__ void k_fill(const int* __restrict__ ei) {
    int e = blockIdx.x * blockDim.x + threadIdx.x;
    if (e < E_EDGES) {
        int d = ei[E_EDGES + e];
        int p = atomicAdd(&g_cursor[d], 1);
        g_csr[p] = ei[e];
    }
}

// ===================== dual bf16-split GEMM =================================
// Computes xr = A @ Wr^T and xo = A @ Wo^T in one pass (A tile shared).
// bf16 2-way split of both operands; 3 products (hh + hl + lh) ~ 16-bit
// mantissa accuracy, fp32 accumulate.
#define SPAD 24   // bf16 row stride: banks (12r + t4) mod 32 distinct per quad

__device__ __forceinline__ void mma16(float* c, const unsigned* a,
                                      unsigned b0, unsigned b1) {
    asm volatile(
        "mma.sync.aligned.m16n8k16.row.col.f32.bf16.bf16.f32 "
        "{%0,%1,%2,%3},{%4,%5,%6,%7},{%8,%9},{%0,%1,%2,%3};"
        : "+f"(c[0]), "+f"(c[1]), "+f"(c[2]), "+f"(c[3])
        : "r"(a[0]), "r"(a[1]), "r"(a[2]), "r"(a[3]), "r"(b0), "r"(b1));
}

__device__ __forceinline__ void split2(float4 v, unsigned& h01, unsigned& h23,
                                       unsigned& l01, unsigned& l23) {
    __nv_bfloat162 h0 = __floats2bfloat162_rn(v.x, v.y);
    __nv_bfloat162 h1 = __floats2bfloat162_rn(v.z, v.w);
    float rx = v.x - __bfloat162float(__low2bfloat16(h0));
    float ry = v.y - __bfloat162float(__high2bfloat16(h0));
    float rz = v.z - __bfloat162float(__low2bfloat16(h1));
    float rw = v.w - __bfloat162float(__high2bfloat16(h1));
    __nv_bfloat162 l0 = __floats2bfloat162_rn(rx, ry);
    __nv_bfloat162 l1 = __floats2bfloat162_rn(rz, rw);
    h01 = *(unsigned*)&h0; h23 = *(unsigned*)&h1;
    l01 = *(unsigned*)&l0; l23 = *(unsigned*)&l1;
}

__global__ __launch_bounds__(256) void k_gemm_dual(
    const float* __restrict__ A,
    const float* __restrict__ Wr, const float* __restrict__ Wo,
    float* __restrict__ xr, float* __restrict__ xo, int M)
{
    __shared__ __align__(16) __nv_bfloat16 sAh[128][SPAD];
    __shared__ __align__(16) __nv_bfloat16 sAl[128][SPAD];
    __shared__ __align__(16) __nv_bfloat16 sBh[256][SPAD];  // 0-127 Wr, 128-255 Wo
    __shared__ __align__(16) __nv_bfloat16 sBl[256][SPAD];

    int tid = threadIdx.x;
    int m0 = blockIdx.x * 128;
    int warp = tid >> 5, lane = tid & 31;
    int wm = warp >> 1, wn = warp & 1;       // 4 m-tiles x 2 n-slices
    int gq = lane >> 2, t4 = lane & 3;

    float accR[2][8][4], accO[2][8][4];
#pragma unroll
    for (int i = 0; i < 2; i++)
#pragma unroll
        for (int j = 0; j < 8; j++)
#pragma unroll
            for (int q = 0; q < 4; q++) { accR[i][j][q] = 0.f; accO[i][j][q] = 0.f; }

    for (int kk = 0; kk < FDIM; kk += 16) {
        // ---- load A tile: 128 rows x 16 k = 512 float4, 2/thread ----
#pragma unroll
        for (int i = 0; i < 2; i++) {
            int f = tid + i * 256;
            int r = f >> 2, c4 = f & 3;
            float4 v = make_float4(0.f, 0.f, 0.f, 0.f);
            if (m0 + r < M)
                v = *(const float4*)(A + (size_t)(m0 + r) * FDIM + kk + c4 * 4);
            unsigned h01, h23, l01, l23;
            split2(v, h01, h23, l01, l23);
            *(unsigned*)&sAh[r][c4 * 4]     = h01;
            *(unsigned*)&sAh[r][c4 * 4 + 2] = h23;
            *(unsigned*)&sAl[r][c4 * 4]     = l01;
            *(unsigned*)&sAl[r][c4 * 4 + 2] = l23;
        }
        // ---- load W tiles: 256 rows x 16 k = 1024 float4, 4/thread ----
#pragma unroll
        for (int i = 0; i < 4; i++) {
            int f = tid + i * 256;
            int n = f >> 2, c4 = f & 3;
            const float* src = (n < 128) ? (Wr + (size_t)n * FDIM)
                                         : (Wo + (size_t)(n - 128) * FDIM);
            float4 v = *(const float4*)(src + kk + c4 * 4);
            unsigned h01, h23, l01, l23;
            split2(v, h01, h23, l01, l23);
            *(unsigned*)&sBh[n][c4 * 4]     = h01;
            *(unsigned*)&sBh[n][c4 * 4 + 2] = h23;
            *(unsigned*)&sBl[n][c4 * 4]     = l01;
            *(unsigned*)&sBl[n][c4 * 4 + 2] = l23;
        }
        __syncthreads();

        // ---- A fragments (hi & lo planes) ----
        unsigned ah[2][4], al[2][4];
#pragma unroll
        for (int mt = 0; mt < 2; mt++) {
            int r = wm * 32 + mt * 16 + gq;
            ah[mt][0] = *(unsigned*)&sAh[r][2 * t4];
            ah[mt][1] = *(unsigned*)&sAh[r + 8][2 * t4];
            ah[mt][2] = *(unsigned*)&sAh[r][2 * t4 + 8];
            ah[mt][3] = *(unsigned*)&sAh[r + 8][2 * t4 + 8];
            al[mt][0] = *(unsigned*)&sAl[r][2 * t4];
            al[mt][1] = *(unsigned*)&sAl[r + 8][2 * t4];
            al[mt][2] = *(unsigned*)&sAl[r][2 * t4 + 8];
            al[mt][3] = *(unsigned*)&sAl[r + 8][2 * t4 + 8];
        }
        // ---- 8 n-tiles per matrix for this warp's 64-col slice ----
#pragma unroll
        for (int nt = 0; nt < 8; nt++) {
            int nR = wn * 64 + nt * 8 + gq;          // Wr row
            int nO = 128 + nR;                        // Wo row
            unsigned bh0 = *(unsigned*)&sBh[nR][2 * t4];
            unsigned bh1 = *(unsigned*)&sBh[nR][2 * t4 + 8];
            unsigned bl0 = *(unsigned*)&sBl[nR][2 * t4];
            unsigned bl1 = *(unsigned*)&sBl[nR][2 * t4 + 8];
            unsigned ch0 = *(unsigned*)&sBh[nO][2 * t4];
            unsigned ch1 = *(unsigned*)&sBh[nO][2 * t4 + 8];
            unsigned cl0 = *(unsigned*)&sBl[nO][2 * t4];
            unsigned cl1 = *(unsigned*)&sBl[nO][2 * t4 + 8];
#pragma unroll
            for (int mt = 0; mt < 2; mt++) {
                mma16(accR[mt][nt], al[mt], bh0, bh1);
                mma16(accR[mt][nt], ah[mt], bl0, bl1);
                mma16(accR[mt][nt], ah[mt], bh0, bh1);
                mma16(accO[mt][nt], al[mt], ch0, ch1);
                mma16(accO[mt][nt], ah[mt], cl0, cl1);
                mma16(accO[mt][nt], ah[mt], ch0, ch1);
            }
        }
        __syncthreads();
    }

    // ---- epilogue ----
#pragma unroll
    for (int mt = 0; mt < 2; mt++) {
#pragma unroll
        for (int nt = 0; nt < 8; nt++) {
            int r0 = m0 + wm * 32 + mt * 16 + gq;
            int cc = wn * 64 + nt * 8 + t4 * 2;
            if (r0 < M) {
                float2 o;
                o.x = accR[mt][nt][0]; o.y = accR[mt][nt][1];
                *(float2*)(xr + (size_t)r0 * FDIM + cc) = o;
                o.x = accO[mt][nt][0]; o.y = accO[mt][nt][1];
                *(float2*)(xo + (size_t)r0 * FDIM + cc) = o;
            }
            if (r0 + 8 < M) {
                float2 o;
                o.x = accR[mt][nt][2]; o.y = accR[mt][nt][3];
                *(float2*)(xr + (size_t)(r0 + 8) * FDIM + cc) = o;
                o.x = accO[mt][nt][2]; o.y = accO[mt][nt][3];
                *(float2*)(xo + (size_t)(r0 + 8) * FDIM + cc) = o;
            }
        }
    }
}

// ----- fused: out_i = relu( sum_{j->i} xr[j] + xo[i] + bias ) ---------------
__global__ void k_agg_combine(const float* __restrict__ xr,
                              const float* __restrict__ xo,
                              const float* __restrict__ bias,
                              float* __restrict__ out)
{
    int node = (blockIdx.x * blockDim.x + threadIdx.x) >> 5;
    if (node >= N_NODES) return;
    int lane = threadIdx.x & 31;
    int beg = g_rowptr[node];
    int end = g_rowptr[node + 1];
    float4 acc = make_float4(0.f, 0.f, 0.f, 0.f);
    int e = beg;
    for (; e + 2 <= end; e += 2) {
        int s0 = g_csr[e];
        int s1 = g_csr[e + 1];
        float4 v0 = __ldg((const float4*)(xr + (size_t)s0 * FDIM) + lane);
        float4 v1 = __ldg((const float4*)(xr + (size_t)s1 * FDIM) + lane);
        acc.x += v0.x + v1.x; acc.y += v0.y + v1.y;
        acc.z += v0.z + v1.z; acc.w += v0.w + v1.w;
    }
    if (e < end) {
        int s0 = g_csr[e];
        float4 v0 = __ldg((const float4*)(xr + (size_t)s0 * FDIM) + lane);
        acc.x += v0.x; acc.y += v0.y; acc.z += v0.z; acc.w += v0.w;
    }
    float4 o = __ldg((const float4*)(xo + (size_t)node * FDIM) + lane);
    float4 b = __ldg((const float4*)bias + lane);
    float4 r;
    r.x = fmaxf(acc.x + o.x + b.x, 0.f);
    r.y = fmaxf(acc.y + o.y + b.y, 0.f);
    r.z = fmaxf(acc.z + o.z + b.z, 0.f);
    r.w = fmaxf(acc.w + o.w + b.w, 0.f);
    ((float4*)(out + (size_t)node * FDIM))[lane] = r;
}

// -------------------- mean pool (sorted batch ids, 4 row-stripes) -----------
__global__ void k_pool(const float* __restrict__ h, const int* __restrict__ batch) {
    int g = blockIdx.x;
    int t = threadIdx.x;                 // 0..511
    int col = t & 127, stripe = t >> 7;  // 4 stripes
    int lo, hi;
    {
        int key = g;
        int a = 0, b = N_NODES;
        while (a < b) { int m = (a + b) >> 1; if (batch[m] < key) a = m + 1; else b = m; }
        lo = a;
        key = g + 1; a = lo; b = N_NODES;
        while (a < b) { int m = (a + b) >> 1; if (batch[m] < key) a = m + 1; else b = m; }
        hi = a;
    }
    float s = 0.f;
    for (int n = lo + stripe; n < hi; n += 4) s += h[(size_t)n * FDIM + col];
    __shared__ float red[4][FDIM];
    red[stripe][col] = s;
    __syncthreads();
    if (stripe == 0) {
        float tot = red[0][col] + red[1][col] + red[2][col] + red[3][col];
        float c = (float)max(hi - lo, 1);
        g_pooled[g * FDIM + col] = tot / c;
    }
}

// -------------------- MLP head + log_softmax --------------------------------
__global__ void k_mlp(const float* __restrict__ Wl1, const float* __restrict__ bl1,
                      const float* __restrict__ Wl2, const float* __restrict__ bl2,
                      float* __restrict__ out)
{
    int g = blockIdx.x;
    int t = threadIdx.x;
    __shared__ float p[FDIM];
    __shared__ float h1[64];
    __shared__ float lg[COUT];
    p[t]      = g_pooled[g * FDIM + t];
    p[t + 64] = g_pooled[g * FDIM + 64 + t];
    __syncthreads();
    float s = bl1[t];
#pragma unroll 8
    for (int k = 0; k < FDIM; k++) s += p[k] * Wl1[t * FDIM + k];
    h1[t] = fmaxf(s, 0.f);
    __syncthreads();
    if (t < COUT) {
        float s2 = bl2[t];
#pragma unroll 8
        for (int k = 0; k < 64; k++) s2 += h1[k] * Wl2[t * 64 + k];
        lg[t] = s2;
    }
    __syncthreads();
    if (t == 0) {
        float mx = -INFINITY;
        for (int c = 0; c < COUT; c++) mx = fmaxf(mx, lg[c]);
        float se = 0.f;
        for (int c = 0; c < COUT; c++) se += expf(lg[c] - mx);
        float lse = logf(se) + mx;
        for (int c = 0; c < COUT; c++) out[g * COUT + c] = lg[c] - lse;
    }
}

// -------------------- launch ------------------------------------------------
extern "C" void kernel_launch(void* const* d_in, const int* in_sizes, int n_in,
                              void* d_out, int out_size)
{
    const float* x     = (const float*)d_in[0];
    const int*   ei    = (const int*)d_in[1];
    const int*   batch = (const int*)d_in[2];
    int wb = 3;
    if (n_in > 3 && in_sizes[3] <= 4) wb = 4;
    const float* W1r = (const float*)d_in[wb + 0];
    const float* b1  = (const float*)d_in[wb + 1];
    const float* W1o = (const float*)d_in[wb + 2];
    const float* W2r = (const float*)d_in[wb + 3];
    const float* b2  = (const float*)d_in[wb + 4];
    const float* W2o = (const float*)d_in[wb + 5];
    const float* W3r = (const float*)d_in[wb + 6];
    const float* b3  = (const float*)d_in[wb + 7];
    const float* W3o = (const float*)d_in[wb + 8];
    const float* Wl1 = (const float*)d_in[wb + 9];
    const float* bl1 = (const float*)d_in[wb + 10];
    const float* Wl2 = (const float*)d_in[wb + 11];
    const float* bl2 = (const float*)d_in[wb + 12];
    float* out = (float*)d_out;

    float *xr, *xo, *hA, *hB;
    cudaGetSymbolAddress((void**)&xr, g_xr);
    cudaGetSymbolAddress((void**)&xo, g_xo);
    cudaGetSymbolAddress((void**)&hA, g_hA);
    cudaGetSymbolAddress((void**)&hB, g_hB);

    // CSR build (once, reused by all 3 layers)
    k_zero_deg<<<(N_NODES + 255) / 256, 256>>>();
    k_hist<<<(E_EDGES + 255) / 256, 256>>>(ei);
    k_scan<<<1, 1024>>>();
    k_fill<<<(E_EDGES + 255) / 256, 256>>>(ei);

    int gemmBlocks = (N_NODES + 127) / 128;
    int aggBlocks  = (N_NODES * 32 + 255) / 256;

    // layer 1
    k_gemm_dual<<<gemmBlocks, 256>>>(x, W1r, W1o, xr, xo, N_NODES);
    k_agg_combine<<<aggBlocks, 256>>>(xr, xo, b1, hA);
    // layer 2
    k_gemm_dual<<<gemmBlocks, 256>>>(hA, W2r, W2o, xr, xo, N_NODES);
    k_agg_combine<<<aggBlocks, 256>>>(xr, xo, b2, hB);
    // layer 3
    k_gemm_dual<<<gemmBlocks, 256>>>(hB, W3r, W3o, xr, xo, N_NODES);
    k_agg_combine<<<aggBlocks, 256>>>(xr, xo, b3, hA);

    // pool + head
    k_pool<<<GGRAPHS, 512>>>(hA, batch);
    k_mlp<<<GGRAPHS, 64>>>(Wl1, bl1, Wl2, bl2, out);
}